// round 1
// baseline (speedup 1.0000x reference)
#include <cuda_runtime.h>

#define NEG_INF __int_as_float(0xff800000)

#define TY 4
#define XS 34            // smem img row stride (floats)
#define CSTRIDE (6*XS)   // 204 floats per channel tile (6 rows)

// Block: 256 threads = 32 x-lanes  x  8 oq-groups.
// Each thread computes outputs for 2 o-channels (oq, oq+8 within the 16-o half)
// and TY=4 consecutive output rows -> 8 outputs/thread.
// Grid: (ohalf=2, ytile=8, b=8) = 128 blocks.
__global__ __launch_bounds__(256, 2)
void bconv_kernel(const float* __restrict__ img,
                  const float* __restrict__ ker,
                  float* __restrict__ out)
{
    __shared__ float simg[32 * CSTRIDE];   // 26112 B: img tile, 32 c x 6 rows x 34 cols (padded)
    __shared__ float sker[32 * 144];       // 18432 B: flipped kernel half: [c][p][oq][j]

    const int ohalf = blockIdx.x;
    const int ytile = blockIdx.y;
    const int b     = blockIdx.z;
    const int tid   = threadIdx.x;
    const int x     = tid & 31;
    const int oq    = tid >> 5;
    const int y0    = ytile * TY;
    const int obase = ohalf * 16;

    // ---- load image tile: c=0..31, global rows y0-1 .. y0+4, cols -1..32 (-inf pad) ----
    const float* gimg = img + b * 32 * 32 * 32;
    for (int idx = tid; idx < 32 * 6 * 34; idx += 256) {
        int c   = idx / CSTRIDE;
        int rem = idx - c * CSTRIDE;
        int r   = rem / XS;
        int xx  = rem - r * XS;
        int h   = y0 - 1 + r;
        int w   = xx - 1;
        float v = NEG_INF;
        if ((unsigned)h < 32u && (unsigned)w < 32u)
            v = gimg[(c * 32 + h) * 32 + w];
        simg[idx] = v;
    }

    // ---- load flipped kernel half into smem, interleaved so (oq, oq+8) form a float2 ----
    // sker[c*144 + p*16 + oql*2 + j] = ker[obase+oql+8*j][c][2-dy][2-dx],  p = dy*3+dx
    for (int idx = tid; idx < 32 * 144; idx += 256) {
        int c   = idx / 144;
        int rem = idx - c * 144;
        int p   = rem >> 4;
        int ol  = rem & 15;
        int oql = ol >> 1;
        int j   = ol & 1;
        int o   = obase + oql + 8 * j;
        int dy  = p / 3, dx = p - dy * 3;
        sker[idx] = ker[((o * 32 + c) * 3 + (2 - dy)) * 3 + (2 - dx)];
    }
    __syncthreads();

    float acc0[TY], acc1[TY];
#pragma unroll
    for (int i = 0; i < TY; i++) { acc0[i] = NEG_INF; acc1[i] = NEG_INF; }

    const float2* sk2 = (const float2*)sker;   // index: c*72 + p*8 + oq  (warp-uniform -> broadcast)

    for (int c = 0; c < 32; c++) {
        float2 kv[9];
#pragma unroll
        for (int p = 0; p < 9; p++) kv[p] = sk2[c * 72 + p * 8 + oq];

        const float* ip = simg + c * CSTRIDE + x;
        float v[6][3];
#pragma unroll
        for (int r = 0; r < 6; r++) {
#pragma unroll
            for (int d = 0; d < 3; d++) v[r][d] = ip[r * XS + d];
        }

#pragma unroll
        for (int yy = 0; yy < TY; yy++) {
#pragma unroll
            for (int dy = 0; dy < 3; dy++) {
#pragma unroll
                for (int dx = 0; dx < 3; dx++) {
                    float vv = v[yy + dy][dx];
                    const float2 k = kv[dy * 3 + dx];
                    acc0[yy] = fmaxf(acc0[yy], vv + k.x);
                    acc1[yy] = fmaxf(acc1[yy], vv + k.y);
                }
            }
        }
    }

    // ---- write out: o = obase+oq (acc0) and obase+oq+8 (acc1) ----
    float* gout = out + ((b * 32 + obase + oq) * 32 + y0) * 32 + x;
#pragma unroll
    for (int yy = 0; yy < TY; yy++) gout[yy * 32] = acc0[yy];
    gout += 8 * 32 * 32;
#pragma unroll
    for (int yy = 0; yy < TY; yy++) gout[yy * 32] = acc1[yy];
}

extern "C" void kernel_launch(void* const* d_in, const int* in_sizes, int n_in,
                              void* d_out, int out_size)
{
    const float* img = (const float*)d_in[0];
    const float* ker = (const float*)d_in[1];
    float*       out = (float*)d_out;
    dim3 grid(2, 8, 8);   // (ohalf, ytile, batch)
    bconv_kernel<<<grid, 256>>>(img, ker, out);
}